// round 3
// baseline (speedup 1.0000x reference)
#include <cuda_runtime.h>
#include <cstdint>
#include <cstddef>

#define B_   1024
#define S_   100
#define H_   512
#define G3   1536
#define NU   1000

// ---------------- scratch (static device memory; no allocations) ----------------
__device__ float g_out[(size_t)B_ * S_ * H_];     // [B,S,H] (h state lives here)
__device__ unsigned g_gbarc[8];                   // per-group barrier count
__device__ unsigned g_gbarg[8];                   // per-group barrier generation

// ---------------- helpers ----------------
__device__ __forceinline__ void mma8(float c[4], const uint32_t a[4], const uint32_t b[2]) {
    asm volatile(
        "mma.sync.aligned.m16n8k8.row.col.f32.tf32.tf32.f32 "
        "{%0,%1,%2,%3}, {%4,%5,%6,%7}, {%8,%9}, {%0,%1,%2,%3};\n"
        : "+f"(c[0]), "+f"(c[1]), "+f"(c[2]), "+f"(c[3])
        : "r"(a[0]), "r"(a[1]), "r"(a[2]), "r"(a[3]), "r"(b[0]), "r"(b[1]));
}
__device__ __forceinline__ void cpa16(uint32_t s, const void* g) {
    asm volatile("cp.async.cg.shared.global [%0], [%1], 16;\n" :: "r"(s), "l"(g));
}
__device__ __forceinline__ void cp_commit() { asm volatile("cp.async.commit_group;\n"); }
template<int N> __device__ __forceinline__ void cp_wait() {
    asm volatile("cp.async.wait_group %0;\n" :: "n"(N));
}
__device__ __forceinline__ uint32_t fasu(float x) { return __float_as_uint(x); }
__device__ __forceinline__ float sigf(float x)  { return 1.0f / (1.0f + __expf(-x)); }
__device__ __forceinline__ float tanhc(float x) { return 1.0f - 2.0f / (__expf(2.0f * x) + 1.0f); }

// =====================================================================
// Fused persistent GRU: per step t, gates = [h_{t-1}, x_t] @ [Whh; Wih]
// (K=1024). n-gate keeps separate x/h accumulators (r,z fuse).
// Grid: 128 CTAs = 8 batch-tiles(128) x 16 col-tiles(32 hcols = 96 gate rows).
// Warp tile 32x48 (warps 4x2). cp.async double buffer, KC=64.
// Barrier only within the 16 CTAs sharing a batch-tile.
// =====================================================================
#define KC2   64
#define LDP2  68
#define STG2  15232          // floats per stage: A 128*68 + B 96*68
#define BOFF  8704           // B region offset within stage (floats)
#define GHS   132            // epilogue staging row stride

__global__ void __launch_bounds__(256, 1)
gru_fused_kernel(const float* __restrict__ hidden,
                 const float* __restrict__ Whh,
                 const float* __restrict__ Wih,
                 const float* __restrict__ bhh,
                 const float* __restrict__ bih,
                 const float* __restrict__ reps) {
    extern __shared__ float sm[];
    const uint32_t smb = (uint32_t)__cvta_generic_to_shared(sm);
    __shared__ float sb[128];    // combined biases (persist across steps)

    const int cta  = blockIdx.x;
    const int b0   = (cta >> 4) * 128;
    const int col0 = (cta & 15) * 32;
    const int grp  = cta >> 4;
    const int tid  = threadIdx.x;
    const int lane = tid & 31;
    const int w    = tid >> 5;
    const int g    = lane >> 2;
    const int t4   = lane & 3;
    const int wm   = (w >> 1) * 32;
    const int wn   = (w & 1) * 48;
    const bool hiwarp = (wn == 48);

    // loader lane geometry (16 float4 per row of 64 cols)
    const int lr0 = tid >> 4;          // base row
    const int lc4 = (tid & 15) * 4;    // col within chunk

    if (tid < 32) {
        int jc = col0 + tid;
        sb[tid]      = bih[jc]        + bhh[jc];
        sb[32 + tid] = bih[512 + jc]  + bhh[512 + jc];
        sb[64 + tid] = bih[1024 + jc];
        sb[96 + tid] = bhh[1024 + jc];
    }
    __syncthreads();

    unsigned gen = *((volatile unsigned*)&g_gbarg[grp]);

    for (int t = 0; t < S_; t++) {
        // ---- operand pipeline ----
        auto issue = [&](int s, int ch) {
            uint32_t base = smb + (uint32_t)s * (STG2 * 4);
            if (ch < 8) {                 // hidden phase: A=h_{t-1}, B=Whh
                int kc = ch * KC2;
#pragma unroll
                for (int i = 0; i < 8; i++) {
                    int rA = lr0 + i * 16;
                    const float* src = (t == 0)
                        ? hidden + (size_t)(b0 + rA) * 512 + lc4 + kc
                        : g_out + ((size_t)(b0 + rA) * S_ + (t - 1)) * 512 + lc4 + kc;
                    cpa16(base + (uint32_t)(rA * LDP2 + lc4) * 4u, src);
                }
#pragma unroll
                for (int i = 0; i < 6; i++) {
                    int rB = lr0 + i * 16;
                    int grow = (rB >> 5) * 512 + col0 + (rB & 31);
                    cpa16(base + (uint32_t)(BOFF + rB * LDP2 + lc4) * 4u,
                          Whh + (size_t)grow * 512 + lc4 + kc);
                }
            } else {                      // input phase: A=x_t, B=Wih
                int kc = (ch - 8) * KC2;
#pragma unroll
                for (int i = 0; i < 8; i++) {
                    int rA = lr0 + i * 16;
                    cpa16(base + (uint32_t)(rA * LDP2 + lc4) * 4u,
                          reps + ((size_t)(b0 + rA) * S_ + t) * 512 + lc4 + kc);
                }
#pragma unroll
                for (int i = 0; i < 6; i++) {
                    int rB = lr0 + i * 16;
                    int grow = (rB >> 5) * 512 + col0 + (rB & 31);
                    cpa16(base + (uint32_t)(BOFF + rB * LDP2 + lc4) * 4u,
                          Wih + (size_t)grow * 512 + lc4 + kc);
                }
            }
        };

        float c[2][6][4];     // r,z(,n-hidden) accumulators
        float c2[2][4][4];    // n-gate x-part (hiwarp only)
#pragma unroll
        for (int i = 0; i < 2; i++)
#pragma unroll
            for (int j = 0; j < 6; j++)
#pragma unroll
                for (int k = 0; k < 4; k++) c[i][j][k] = 0.0f;
#pragma unroll
        for (int i = 0; i < 2; i++)
#pragma unroll
            for (int j = 0; j < 4; j++)
#pragma unroll
                for (int k = 0; k < 4; k++) c2[i][j][k] = 0.0f;

        issue(0, 0); cp_commit();
        for (int ch = 0; ch < 16; ch++) {
            if (ch < 15) { issue((ch + 1) & 1, ch + 1); cp_commit(); cp_wait<1>(); }
            else cp_wait<0>();
            __syncthreads();
            const float* A  = sm + (ch & 1) * STG2;
            const float* Bs = A + BOFF;
#pragma unroll
            for (int kk = 0; kk < KC2; kk += 8) {
                uint32_t a[2][4], b[6][2];
#pragma unroll
                for (int mt = 0; mt < 2; mt++) {
                    int rb = wm + mt * 16;
                    a[mt][0] = fasu(A[(rb + g    ) * LDP2 + kk + t4]);
                    a[mt][1] = fasu(A[(rb + g + 8) * LDP2 + kk + t4]);
                    a[mt][2] = fasu(A[(rb + g    ) * LDP2 + kk + 4 + t4]);
                    a[mt][3] = fasu(A[(rb + g + 8) * LDP2 + kk + 4 + t4]);
                }
#pragma unroll
                for (int nt = 0; nt < 6; nt++) {
                    int nb = wn + nt * 8 + g;
                    b[nt][0] = fasu(Bs[nb * LDP2 + kk + t4]);
                    b[nt][1] = fasu(Bs[nb * LDP2 + kk + 4 + t4]);
                }
                if (ch < 8) {            // hidden phase: all into c
#pragma unroll
                    for (int mt = 0; mt < 2; mt++)
#pragma unroll
                        for (int nt = 0; nt < 6; nt++) mma8(c[mt][nt], a[mt], b[nt]);
                } else {                 // x phase: n-cols (hiwarp nt>=2) into c2
                    if (!hiwarp) {
#pragma unroll
                        for (int mt = 0; mt < 2; mt++)
#pragma unroll
                            for (int nt = 0; nt < 6; nt++) mma8(c[mt][nt], a[mt], b[nt]);
                    } else {
#pragma unroll
                        for (int mt = 0; mt < 2; mt++) {
                            mma8(c[mt][0], a[mt], b[0]);
                            mma8(c[mt][1], a[mt], b[1]);
#pragma unroll
                            for (int q = 0; q < 4; q++) mma8(c2[mt][q], a[mt], b[q + 2]);
                        }
                    }
                }
            }
            __syncthreads();
        }

        // ---- stage accumulators to smem (stride GHS) ----
        float* gh = sm;
#pragma unroll
        for (int mt = 0; mt < 2; mt++) {
#pragma unroll
            for (int nt = 0; nt < 6; nt++) {
                int row = wm + mt * 16 + g;
                int col = wn + nt * 8 + 2 * t4;
                *(float2*)&gh[row * GHS + col]       = make_float2(c[mt][nt][0], c[mt][nt][1]);
                *(float2*)&gh[(row + 8) * GHS + col] = make_float2(c[mt][nt][2], c[mt][nt][3]);
            }
        }
        if (hiwarp) {
#pragma unroll
            for (int mt = 0; mt < 2; mt++) {
#pragma unroll
                for (int q = 0; q < 4; q++) {
                    int row = wm + mt * 16 + g;
                    int col = 96 + q * 8 + 2 * t4;
                    *(float2*)&gh[row * GHS + col]       = make_float2(c2[mt][q][0], c2[mt][q][1]);
                    *(float2*)&gh[(row + 8) * GHS + col] = make_float2(c2[mt][q][2], c2[mt][q][3]);
                }
            }
        }
        __syncthreads();

        // ---- gates epilogue: 128 rows x 32 cols ----
        {
            const int erow = tid >> 1;
            const int jh   = (tid & 1) * 16;
            const int bb   = b0 + erow;
            const float* hp = (t == 0)
                ? hidden + (size_t)bb * 512 + col0 + jh
                : g_out + ((size_t)bb * S_ + (t - 1)) * 512 + col0 + jh;
            size_t ob = ((size_t)bb * S_ + t) * 512 + col0 + jh;
#pragma unroll
            for (int q = 0; q < 4; q++) {
                int j = jh + q * 4;
                float4 cr  = *(float4*)&gh[erow * GHS + j];
                float4 cz  = *(float4*)&gh[erow * GHS + 32 + j];
                float4 cnh = *(float4*)&gh[erow * GHS + 64 + j];
                float4 cnx = *(float4*)&gh[erow * GHS + 96 + j];
                float4 brz = *(float4*)&sb[j];
                float4 bzz = *(float4*)&sb[32 + j];
                float4 bnx = *(float4*)&sb[64 + j];
                float4 bnh = *(float4*)&sb[96 + j];
                float4 hv  = *(const float4*)&hp[q * 4];
                float4 o;
                {
                    float r = sigf(cr.x + brz.x);
                    float z = sigf(cz.x + bzz.x);
                    float n = tanhc((cnx.x + bnx.x) + r * (cnh.x + bnh.x));
                    o.x = (1.0f - z) * n + z * hv.x;
                }
                {
                    float r = sigf(cr.y + brz.y);
                    float z = sigf(cz.y + bzz.y);
                    float n = tanhc((cnx.y + bnx.y) + r * (cnh.y + bnh.y));
                    o.y = (1.0f - z) * n + z * hv.y;
                }
                {
                    float r = sigf(cr.z + brz.z);
                    float z = sigf(cz.z + bzz.z);
                    float n = tanhc((cnx.z + bnx.z) + r * (cnh.z + bnh.z));
                    o.z = (1.0f - z) * n + z * hv.z;
                }
                {
                    float r = sigf(cr.w + brz.w);
                    float z = sigf(cz.w + bzz.w);
                    float n = tanhc((cnx.w + bnx.w) + r * (cnh.w + bnh.w));
                    o.w = (1.0f - z) * n + z * hv.w;
                }
                *(float4*)&g_out[ob + q * 4] = o;
            }
        }

        // ---- group barrier (16 CTAs sharing this batch-tile) ----
        if (t < S_ - 1) {
            __syncthreads();
            if (tid == 0) {
                unsigned target = gen + 1;
                __threadfence();
                if (atomicAdd(&g_gbarc[grp], 1u) == 15u) {
                    g_gbarc[grp] = 0;
                    __threadfence();
                    atomicExch(&g_gbarg[grp], target);
                } else {
                    while (*((volatile unsigned*)&g_gbarg[grp]) != target) __nanosleep(32);
                    __threadfence();
                }
                gen = target;
            }
            __syncthreads();
        }
    }
}

// =====================================================================
// Attention: per-batch CTA; 4 passes of 2 o-tiles (128 Wa rows each),
// cp.async B + register-prefetched A, KC=32 double buffer.
// =====================================================================
#define AKC   32
#define ALD   36
#define ASTG  4608     // floats per A (or B) stage

__global__ void __launch_bounds__(256, 2)
attn_kernel(const float* __restrict__ reps,
            const int*   __restrict__ counts,
            const int*   __restrict__ users,
            const float* __restrict__ Wa,
            const float* __restrict__ ba,
            const float* __restrict__ Ws,
            const float* __restrict__ bs,
            float*       __restrict__ outp) {
    extern __shared__ float smA[];   // As[2]:0..9216, Bs[2]:9216..18432
    __shared__ float Rs[128];
    __shared__ float scores_s[128];
    __shared__ float wts[S_];
    __shared__ float inv_s;

    const int b   = blockIdx.x;
    const int u   = users[b];
    const int cnt = counts[b];
    const size_t ub = (size_t)u * 512;
    const float* WaU = Wa + (size_t)u * 512 * 512;

    const int tid  = threadIdx.x;
    const int lane = tid & 31;
    const int w    = tid >> 5;
    const int g    = lane >> 2;
    const int t4   = lane & 3;
    const int wm = w * 16;
    const int s0 = wm + g, s1 = wm + g + 8;
    const bool m0q = (s0 >= cnt), m1q = (s1 >= cnt);

    // loader geometry: 128 rows x 8 float4 per chunk -> 4 slots/thread
    const int lrow = tid >> 3;            // base row
    const int lc4  = (tid & 7) * 4;
    int   arow[4]; bool amask[4]; const float* aptr[4];
#pragma unroll
    for (int i = 0; i < 4; i++) {
        arow[i]  = lrow + i * 32;
        amask[i] = (arow[i] >= cnt);
        aptr[i]  = (arow[i] < S_) ? g_out + ((size_t)b * S_ + arow[i]) * 512 + lc4 : nullptr;
    }

    const uint32_t smb = (uint32_t)__cvta_generic_to_shared(smA);
    float pr0 = 0.0f, pr1 = 0.0f;

    for (int p = 0; p < 4; p++) {
        const int o0 = p * 128;
        float c[2][8][4];
#pragma unroll
        for (int i = 0; i < 2; i++)
#pragma unroll
            for (int j = 0; j < 8; j++)
#pragma unroll
                for (int k = 0; k < 4; k++) c[i][j][k] = 0.0f;
        float rp[4] = {0.0f, 0.0f, 0.0f, 0.0f};

        auto ldA = [&](float4* ra, int kc) {
#pragma unroll
            for (int i = 0; i < 4; i++)
                ra[i] = aptr[i] ? *(const float4*)(aptr[i] + kc)
                                : make_float4(0.f, 0.f, 0.f, 0.f);
        };
        auto stsA = [&](int st, const float4* ra) {
            float* dst = smA + st * ASTG;
#pragma unroll
            for (int i = 0; i < 4; i++) {
                float4 v = ra[i];
                if (amask[i]) {
                    v.x = (v.x - 1e6f) + 1e6f; v.y = (v.y - 1e6f) + 1e6f;
                    v.z = (v.z - 1e6f) + 1e6f; v.w = (v.w - 1e6f) + 1e6f;
                }
                int off = arow[i] * ALD + lc4;
                dst[off] = v.x; dst[off + 1] = v.y; dst[off + 2] = v.z; dst[off + 3] = v.w;
            }
        };
        auto cpaB = [&](int st, int kc) {
            uint32_t base = smb + (uint32_t)(2 * ASTG + st * ASTG) * 4u;
#pragma unroll
            for (int i = 0; i < 4; i++) {
                int brow = arow[i];
                cpa16(base + (uint32_t)(brow * ALD + lc4) * 4u,
                      WaU + (size_t)(o0 + brow) * 512 + lc4 + kc);
            }
        };

        float4 ra[4];
        ldA(ra, 0);
        stsA(0, ra);
        cpaB(0, 0); cp_commit();
        for (int k = 0; k < 16; k++) {
            if (k < 15) ldA(ra, (k + 1) * AKC);
            cp_wait<0>();
            __syncthreads();
            const float* Ast = smA + (k & 1) * ASTG;
            const float* Bst = smA + 2 * ASTG + (k & 1) * ASTG;
            // accumulate Wa row-sums from arrived smem
#pragma unroll
            for (int i = 0; i < 4; i++) {
                float4 v = *(const float4*)&Bst[arow[i] * ALD + lc4];
                rp[i] += v.x + v.y + v.z + v.w;
            }
#pragma unroll
            for (int kk = 0; kk < AKC; kk += 8) {
                uint32_t a[4];
                a[0] = fasu(Ast[(wm + g    ) * ALD + kk + t4]);
                a[1] = fasu(Ast[(wm + g + 8) * ALD + kk + t4]);
                a[2] = fasu(Ast[(wm + g    ) * ALD + kk + 4 + t4]);
                a[3] = fasu(Ast[(wm + g + 8) * ALD + kk + 4 + t4]);
#pragma unroll
                for (int ot = 0; ot < 2; ot++)
#pragma unroll
                    for (int nt = 0; nt < 8; nt++) {
                        int nb = ot * 64 + nt * 8 + g;
                        uint32_t bf[2];
                        bf[0] = fasu(Bst[nb * ALD + kk + t4]);
                        bf[1] = fasu(Bst[nb * ALD + kk + 4 + t4]);
                        mma8(c[ot][nt], a, bf);
                    }
            }
            __syncthreads();
            if (k < 15) { stsA((k + 1) & 1, ra); cpaB((k + 1) & 1, (k + 1) * AKC); cp_commit(); }
        }

        // finish R row-sums (8 lanes share a row)
#pragma unroll
        for (int i = 0; i < 4; i++) {
            float v = rp[i];
            v += __shfl_xor_sync(0xffffffffu, v, 1);
            v += __shfl_xor_sync(0xffffffffu, v, 2);
            v += __shfl_xor_sync(0xffffffffu, v, 4);
            if ((tid & 7) == 0) Rs[(tid >> 3) + i * 32] = v;
        }
        __syncthreads();

        // epilogue: e = tanh(acc + bias), accumulate e*Ws
#pragma unroll
        for (int ot = 0; ot < 2; ot++) {
#pragma unroll
            for (int nt = 0; nt < 8; nt++) {
                int cl  = ot * 64 + nt * 8 + 2 * t4;
                int col = o0 + cl;
                float baa = ba[ub + col], bab = ba[ub + col + 1];
                float Ca = baa - 1e6f * Rs[cl];
                float Cb = bab - 1e6f * Rs[cl + 1];
                float wsa = Ws[ub + col], wsb = Ws[ub + col + 1];
                pr0 += tanhc(c[ot][nt][0] + (m0q ? Ca : baa)) * wsa
                     + tanhc(c[ot][nt][1] + (m0q ? Cb : bab)) * wsb;
                pr1 += tanhc(c[ot][nt][2] + (m1q ? Ca : baa)) * wsa
                     + tanhc(c[ot][nt][3] + (m1q ? Cb : bab)) * wsb;
            }
        }
        __syncthreads();
    }

    pr0 += __shfl_xor_sync(0xffffffffu, pr0, 1);
    pr0 += __shfl_xor_sync(0xffffffffu, pr0, 2);
    pr1 += __shfl_xor_sync(0xffffffffu, pr1, 1);
    pr1 += __shfl_xor_sync(0xffffffffu, pr1, 2);
    float bsu = bs[u];
    if (t4 == 0) {
        if (s0 < S_) scores_s[s0] = pr0 + bsu;
        if (s1 < S_) scores_s[s1] = pr1 + bsu;
    }
    __syncthreads();

    if (w == 0) {
        float m = -1e30f;
        for (int s = lane; s < S_; s += 32) m = fmaxf(m, scores_s[s]);
#pragma unroll
        for (int off = 16; off > 0; off >>= 1) m = fmaxf(m, __shfl_xor_sync(0xffffffffu, m, off));
        float sum = 0.0f;
        for (int s = lane; s < S_; s += 32) {
            float e = __expf(scores_s[s] - m);
            wts[s] = e;
            sum += e;
        }
#pragma unroll
        for (int off = 16; off > 0; off >>= 1) sum += __shfl_xor_sync(0xffffffffu, sum, off);
        if (lane == 0) inv_s = 1.0f / sum;
    }
    __syncthreads();

    const float* rb = reps + (size_t)b * S_ * 512;
    float acc0 = 0.0f, acc1 = 0.0f;
    for (int s = 0; s < S_; s++) {
        float wv = wts[s];
        acc0 += wv * rb[(size_t)s * 512 + tid];
        acc1 += wv * rb[(size_t)s * 512 + 256 + tid];
    }
    float inv = inv_s;
    outp[(size_t)b * 512 + tid]       = acc0 * inv;
    outp[(size_t)b * 512 + 256 + tid] = acc1 * inv;
}

// =====================================================================
extern "C" void kernel_launch(void* const* d_in, const int* in_sizes, int n_in,
                              void* d_out, int out_size) {
    (void)in_sizes; (void)n_in; (void)out_size;
    const float* reps   = (const float*)d_in[0];
    const float* hidden = (const float*)d_in[1];
    const int*   counts = (const int*)  d_in[2];
    const int*   users  = (const int*)  d_in[3];
    const float* Whh    = (const float*)d_in[5];
    const float* Wih    = (const float*)d_in[4];
    const float* bih    = (const float*)d_in[6];
    const float* bhh    = (const float*)d_in[7];
    const float* Wa     = (const float*)d_in[8];
    const float* ba     = (const float*)d_in[9];
    const float* Wsc    = (const float*)d_in[10];
    const float* bsc    = (const float*)d_in[11];
    float* outp = (float*)d_out;

    const int SMEM_GRU  = STG2 * 2 * 4;          // 121856 bytes
    const int SMEM_ATTN = ASTG * 4 * 4;          // 73728 bytes
    cudaFuncSetAttribute(gru_fused_kernel, cudaFuncAttributeMaxDynamicSharedMemorySize, SMEM_GRU);
    cudaFuncSetAttribute(attn_kernel, cudaFuncAttributeMaxDynamicSharedMemorySize, SMEM_ATTN);

    gru_fused_kernel<<<128, 256, SMEM_GRU>>>(hidden, Whh, Wih, bhh, bih, reps);
    attn_kernel<<<B_, 256, SMEM_ATTN>>>(reps, counts, users, Wa, ba, Wsc, bsc, outp);
}

// round 5
// speedup vs baseline: 1.2957x; 1.2957x over previous
#include <cuda_runtime.h>
#include <cuda_bf16.h>
#include <cstdint>
#include <cstddef>

#define B_   1024
#define S_   100
#define H_   512
#define NU   1000

// ---------------- scratch (static device memory; no allocations) ----------------
__device__ float         g_out[(size_t)B_ * S_ * H_];    // fp32 GRU outputs [B,S,H]
__device__ __nv_bfloat16 g_xbf[(size_t)B_ * S_ * H_];    // reps bf16
__device__ __nv_bfloat16 g_hbf[2][B_ * H_];              // h state bf16 ping-pong
__device__ __nv_bfloat16 g_wabf[(size_t)NU * H_ * H_];   // Wa bf16
__device__ float         g_R[NU * H_];                   // fp32 Wa row sums
__device__ unsigned char g_wblob[16 * 2 * 4 * 24576];    // GRU W tiles bf16
__device__ unsigned g_gbarc[8];
__device__ unsigned g_gbarg[8];

// ---------------- helpers ----------------
__device__ __forceinline__ void cpa16(uint32_t s, const void* g) {
    asm volatile("cp.async.cg.shared.global [%0], [%1], 16;\n" :: "r"(s), "l"(g));
}
__device__ __forceinline__ void cp_commit() { asm volatile("cp.async.commit_group;\n"); }
template<int N> __device__ __forceinline__ void cp_wait() {
    asm volatile("cp.async.wait_group %0;\n" :: "n"(N));
}
__device__ __forceinline__ float sigf(float x)  { return 1.0f / (1.0f + __expf(-x)); }
__device__ __forceinline__ float tanhc(float x) { return 1.0f - 2.0f / (__expf(2.0f * x) + 1.0f); }

__device__ __forceinline__ void mma16(float c[4], const uint32_t a[4], const uint32_t b[2]) {
    asm volatile(
        "mma.sync.aligned.m16n8k16.row.col.f32.bf16.bf16.f32 "
        "{%0,%1,%2,%3}, {%4,%5,%6,%7}, {%8,%9}, {%0,%1,%2,%3};\n"
        : "+f"(c[0]), "+f"(c[1]), "+f"(c[2]), "+f"(c[3])
        : "r"(a[0]), "r"(a[1]), "r"(a[2]), "r"(a[3]), "r"(b[0]), "r"(b[1]));
}
__device__ __forceinline__ void ldsm4(uint32_t r[4], uint32_t addr) {
    asm volatile("ldmatrix.sync.aligned.m8n8.x4.shared.b16 {%0,%1,%2,%3}, [%4];"
        : "=r"(r[0]), "=r"(r[1]), "=r"(r[2]), "=r"(r[3]) : "r"(addr));
}
__device__ __forceinline__ uint32_t pack_bf(float x, float y) {
    __nv_bfloat162 p = __floats2bfloat162_rn(x, y);
    return *(uint32_t*)&p;
}

// =====================================================================
// Prep kernels
// =====================================================================
__global__ void prep_x(const float4* __restrict__ X) {
    size_t i = (size_t)blockIdx.x * 1024 + threadIdx.x;
    if (i < (size_t)B_ * S_ * H_ / 4) {
        float4 v = X[i];
        uint2 p = make_uint2(pack_bf(v.x, v.y), pack_bf(v.z, v.w));
        *(uint2*)&g_xbf[i * 4] = p;
    }
}
__global__ void prep_h(const float4* __restrict__ Hd) {
    int i = blockIdx.x * 1024 + threadIdx.x;
    if (i < B_ * H_ / 4) {
        float4 v = Hd[i];
        uint2 p = make_uint2(pack_bf(v.x, v.y), pack_bf(v.z, v.w));
        *(uint2*)&g_hbf[0][i * 4] = p;
    }
}
// W blobs: [ct 16][phase 2][chunk 4] of 96 rows x 128 k bf16 (row-major 256B rows)
__global__ void prep_w(const float* __restrict__ Whh, const float* __restrict__ Wih) {
    size_t idx = (size_t)blockIdx.x * 1024 + threadIdx.x;
    if (idx >= (size_t)16 * 2 * 4 * 96 * 128) return;
    int k  = (int)(idx & 127);
    size_t i2 = idx >> 7;
    int r = (int)(i2 % 96); size_t i3 = i2 / 96;
    int c = (int)(i3 & 3);
    size_t i4 = i3 >> 2;
    int p  = (int)(i4 & 1);
    int ct = (int)(i4 >> 1);
    const float* W = p ? Wih : Whh;
    int grow = (r >> 5) * 512 + ct * 32 + (r & 31);
    float v = W[(size_t)grow * 512 + c * 128 + k];
    size_t blob = ((size_t)(ct * 2 + p) * 4 + c) * 24576;
    *(__nv_bfloat16*)(g_wblob + blob + (size_t)r * 256 + k * 2) = __float2bfloat16(v);
}
// Wa -> bf16 + fp32 row sums (one warp per (u,o) row; deterministic)
__global__ void prep_wa(const float* __restrict__ Wa) {
    int gw = blockIdx.x * 8 + (threadIdx.x >> 5);
    int lane = threadIdx.x & 31;
    if (gw >= NU * 512) return;
    const float* src = Wa + (size_t)gw * 512;
    __nv_bfloat16* dst = g_wabf + (size_t)gw * 512;
    float s = 0.0f;
#pragma unroll 4
    for (int i = lane; i < 512; i += 32) {
        float v = src[i];
        s += v;
        dst[i] = __float2bfloat16(v);
    }
#pragma unroll
    for (int off = 16; off > 0; off >>= 1) s += __shfl_xor_sync(0xffffffffu, s, off);
    if (lane == 0) g_R[gw] = s;
}

// =====================================================================
// Persistent GRU (bf16 + ldmatrix + m16n8k16)
// 128 CTAs = 8 batch-groups(128 rows) x 16 col-tiles(32 h-cols).
// Per step: D cols [r(32)|z(32)|nh(32)|nx(32)], K=2x512 via 8 chunks of 128.
// Warp w owns rows 16w..16w+15, all 128 D cols. In-register gate epilogue.
// =====================================================================
#define GSTG 60928           // stage bytes: A 128x272 + B 96x272

__global__ void __launch_bounds__(256)
gru_kernel(const float* __restrict__ hidden,
           const float* __restrict__ bhh,
           const float* __restrict__ bih) {
    extern __shared__ unsigned char dsm[];
    const uint32_t smb = (uint32_t)__cvta_generic_to_shared(dsm);
    __shared__ float sb[128];

    const int cta  = blockIdx.x;
    const int b0   = (cta >> 4) * 128;
    const int ct   = cta & 15;
    const int col0 = ct * 32;
    const int grp  = cta >> 4;
    const int tid  = threadIdx.x;
    const int l    = tid & 31;
    const int w    = tid >> 5;
    const int g    = l >> 2;
    const int tg   = l & 3;
    // ldmatrix per-lane offset (stride 272B)
    const uint32_t loff = (uint32_t)((((l >> 3) & 1) * 8 + (l & 7)) * 272 + (l >> 4) * 16);

    // cp.async slot geometry
    int rowA[8], kuA[8]; uint32_t adst[8];
#pragma unroll
    for (int i = 0; i < 8; i++) {
        int u = tid + i * 256;
        rowA[i] = u >> 4; kuA[i] = (u & 15);
        adst[i] = (uint32_t)(rowA[i] * 272 + kuA[i] * 16);
    }
    uint32_t bdst[6]; uint32_t bsrc[6];
#pragma unroll
    for (int i = 0; i < 6; i++) {
        int u = tid + i * 256;           // < 1536
        bdst[i] = (uint32_t)(34816 + (u >> 4) * 272 + (u & 15) * 16);
        bsrc[i] = (uint32_t)u * 16;
    }

    if (tid < 32) {
        int jc = col0 + tid;
        sb[tid]      = bih[jc] + bhh[jc];
        sb[32 + tid] = bih[512 + jc] + bhh[512 + jc];
        sb[64 + tid] = bhh[1024 + jc];
        sb[96 + tid] = bih[1024 + jc];
    }
    __syncthreads();

    unsigned gen = *((volatile unsigned*)&g_gbarg[grp]);

    for (int t = 0; t < S_; t++) {
        auto issue = [&](int c) {
            uint32_t base = smb + (uint32_t)(c & 1) * GSTG;
            if (c < 4) {
                const __nv_bfloat16* hb = g_hbf[t & 1];
#pragma unroll
                for (int i = 0; i < 8; i++)
                    cpa16(base + adst[i],
                          hb + (size_t)(b0 + rowA[i]) * 512 + c * 128 + kuA[i] * 8);
            } else {
#pragma unroll
                for (int i = 0; i < 8; i++)
                    cpa16(base + adst[i],
                          g_xbf + ((size_t)(b0 + rowA[i]) * S_ + t) * 512 + (c - 4) * 128 + kuA[i] * 8);
            }
            const unsigned char* blob =
                g_wblob + ((size_t)(ct * 2 + (c >> 2)) * 4 + (c & 3)) * 24576;
#pragma unroll
            for (int i = 0; i < 6; i++) cpa16(base + bdst[i], blob + bsrc[i]);
            cp_commit();
        };

        float acc[16][4];
#pragma unroll
        for (int i = 0; i < 16; i++)
#pragma unroll
            for (int j = 0; j < 4; j++) acc[i][j] = 0.0f;

        issue(0); issue(1);
        for (int c = 0; c < 8; c++) {
            if (c < 7) cp_wait<1>(); else cp_wait<0>();
            __syncthreads();
            uint32_t Ab = smb + (uint32_t)(c & 1) * GSTG + (uint32_t)(w * 16) * 272 + loff;
            uint32_t Bb = smb + (uint32_t)(c & 1) * GSTG + 34816 + loff;
            if (c < 4) {
#pragma unroll
                for (int kk = 0; kk < 8; kk++) {
                    uint32_t kb = (uint32_t)kk * 32;     // kk*16 elems * 2B
                    uint32_t a[4]; ldsm4(a, Ab + kb);
                    uint32_t bf[12][2];
#pragma unroll
                    for (int q = 0; q < 6; q++) {
                        uint32_t r4[4]; ldsm4(r4, Bb + (uint32_t)(q * 16) * 272 + kb);
                        bf[2*q][0] = r4[0]; bf[2*q][1] = r4[2];
                        bf[2*q+1][0] = r4[1]; bf[2*q+1][1] = r4[3];
                    }
#pragma unroll
                    for (int f = 0; f < 12; f++) mma16(acc[f], a, bf[f]);
                }
            } else {
#pragma unroll
                for (int kk = 0; kk < 8; kk++) {
                    uint32_t kb = (uint32_t)kk * 32;
                    uint32_t a[4]; ldsm4(a, Ab + kb);
                    uint32_t bf[12][2];
#pragma unroll
                    for (int q = 0; q < 6; q++) {
                        uint32_t r4[4]; ldsm4(r4, Bb + (uint32_t)(q * 16) * 272 + kb);
                        bf[2*q][0] = r4[0]; bf[2*q][1] = r4[2];
                        bf[2*q+1][0] = r4[1]; bf[2*q+1][1] = r4[3];
                    }
#pragma unroll
                    for (int f = 0; f < 8; f++) mma16(acc[f], a, bf[f]);
#pragma unroll
                    for (int f = 8; f < 12; f++) mma16(acc[f + 4], a, bf[f]);
                }
            }
            __syncthreads();
            if (c < 6) issue(c + 2);
        }

        // ---- in-register gate epilogue ----
#pragma unroll
        for (int half = 0; half < 2; half++) {
            int rr = b0 + 16 * w + g + half * 8;
            const float* hp = (t == 0)
                ? hidden + (size_t)rr * 512 + col0
                : g_out + ((size_t)rr * S_ + (t - 1)) * 512 + col0;
            float* op = g_out + ((size_t)rr * S_ + t) * 512 + col0;
            __nv_bfloat16* hb = g_hbf[(t + 1) & 1] + (size_t)rr * 512 + col0;
#pragma unroll
            for (int q = 0; q < 4; q++) {
                int j = 8 * q + 2 * tg;
                float2 hv = *(const float2*)(hp + j);
                float r0 = sigf(acc[q][2*half + 0] + sb[j]);
                float r1 = sigf(acc[q][2*half + 1] + sb[j + 1]);
                float z0 = sigf(acc[4 + q][2*half + 0] + sb[32 + j]);
                float z1 = sigf(acc[4 + q][2*half + 1] + sb[32 + j + 1]);
                float n0 = tanhc((acc[12 + q][2*half + 0] + sb[96 + j]) +
                                 r0 * (acc[8 + q][2*half + 0] + sb[64 + j]));
                float n1 = tanhc((acc[12 + q][2*half + 1] + sb[96 + j + 1]) +
                                 r1 * (acc[8 + q][2*half + 1] + sb[64 + j + 1]));
                float o0 = (1.0f - z0) * n0 + z0 * hv.x;
                float o1 = (1.0f - z1) * n1 + z1 * hv.y;
                *(float2*)(op + j) = make_float2(o0, o1);
                *(uint32_t*)(hb + j) = pack_bf(o0, o1);
            }
        }

        // ---- group barrier ----
        if (t < S_ - 1) {
            __syncthreads();
            if (tid == 0) {
                unsigned target = gen + 1;
                __threadfence();
                if (atomicAdd(&g_gbarc[grp], 1u) == 15u) {
                    g_gbarc[grp] = 0;
                    __threadfence();
                    atomicExch(&g_gbarg[grp], target);
                } else {
                    while (*((volatile unsigned*)&g_gbarg[grp]) != target) __nanosleep(32);
                    __threadfence();
                }
                gen = target;
            }
            __syncthreads();
        }
    }
}

// =====================================================================
// Attention (bf16 + ldmatrix): A (masked GRU out) resident in smem bf16,
// Wa bf16 streamed via 4-deep cp.async. 8 o-passes of 64 cols.
// =====================================================================
#define A_STRIDE 1040        // 512 + 8 pad bf16, bytes
#define B_STRIDE 144         // 64 + 8 pad bf16, bytes
#define B_STG    9216        // 64 rows * 144B
#define ATTN_SM  (133120 + 4 * B_STG)

__global__ void __launch_bounds__(256)
attn_kernel(const float* __restrict__ reps,
            const int*   __restrict__ counts,
            const int*   __restrict__ users,
            const float* __restrict__ ba,
            const float* __restrict__ Ws,
            const float* __restrict__ bs,
            float*       __restrict__ outp) {
    extern __shared__ unsigned char dsm[];
    const uint32_t smb = (uint32_t)__cvta_generic_to_shared(dsm);
    __shared__ float scores_s[128];
    __shared__ float wts[S_];
    __shared__ float inv_s;

    const int b   = blockIdx.x;
    const int u   = users[b];
    const int cnt = counts[b];
    const size_t ub = (size_t)u * 512;
    const __nv_bfloat16* wab = g_wabf + (size_t)u * 512 * 512;

    const int tid = threadIdx.x;
    const int l   = tid & 31;
    const int w   = tid >> 5;
    const int g   = l >> 2;
    const int tg  = l & 3;
    const uint32_t loffA = (uint32_t)((((l >> 3) & 1) * 8 + (l & 7)) * A_STRIDE + (l >> 4) * 16);
    const uint32_t loffB = (uint32_t)((((l >> 3) & 1) * 8 + (l & 7)) * B_STRIDE + (l >> 4) * 16);

    // B loader slots (2 per thread)
    int rB[2], kuB[2];
#pragma unroll
    for (int i = 0; i < 2; i++) {
        int uu = tid + i * 256;
        rB[i] = uu >> 3; kuB[i] = uu & 7;
    }
    auto issueB = [&](int gidx) {
        int pass = gidx >> 3, c = gidx & 7;
        uint32_t base = smb + 133120 + (uint32_t)(gidx & 3) * B_STG;
#pragma unroll
        for (int i = 0; i < 2; i++)
            cpa16(base + (uint32_t)(rB[i] * B_STRIDE + kuB[i] * 16),
                  wab + (size_t)(pass * 64 + rB[i]) * 512 + c * 64 + kuB[i] * 8);
        cp_commit();
    };

    issueB(0); issueB(1); issueB(2);

    // ---- load + convert A resident (rows>=cnt get the -1e6 quantization) ----
    for (int i = 0; i < 64; i++) {
        int uu = tid + i * 256;
        int row = uu >> 7, c4 = (uu & 127) * 4;
        float4 v = make_float4(0.f, 0.f, 0.f, 0.f);
        if (row < S_) {
            v = *(const float4*)&g_out[((size_t)b * S_ + row) * 512 + c4];
            if (row >= cnt) {
                v.x = (v.x - 1e6f) + 1e6f; v.y = (v.y - 1e6f) + 1e6f;
                v.z = (v.z - 1e6f) + 1e6f; v.w = (v.w - 1e6f) + 1e6f;
            }
        }
        *(uint2*)(dsm + (size_t)row * A_STRIDE + c4 * 2) =
            make_uint2(pack_bf(v.x, v.y), pack_bf(v.z, v.w));
    }
    __syncthreads();

    const bool m0 = (16 * w + g >= cnt);
    const bool m1 = (16 * w + 8 + g >= cnt);
    float pr0 = 0.0f, pr1 = 0.0f;

    for (int pass = 0; pass < 8; pass++) {
        float acc[8][4];
#pragma unroll
        for (int i = 0; i < 8; i++)
#pragma unroll
            for (int j = 0; j < 4; j++) acc[i][j] = 0.0f;

        for (int c = 0; c < 8; c++) {
            int gidx = pass * 8 + c;
            if (gidx < 62) cp_wait<2>();
            else if (gidx == 62) cp_wait<1>();
            else cp_wait<0>();
            __syncthreads();
            uint32_t Ab = smb + (uint32_t)(w * 16) * A_STRIDE + loffA + (uint32_t)(c * 64) * 2;
            uint32_t Bb = smb + 133120 + (uint32_t)(gidx & 3) * B_STG + loffB;
#pragma unroll
            for (int kk = 0; kk < 4; kk++) {
                uint32_t a[4]; ldsm4(a, Ab + (uint32_t)kk * 32);
                uint32_t bf[8][2];
#pragma unroll
                for (int q = 0; q < 4; q++) {
                    uint32_t r4[4];
                    ldsm4(r4, Bb + (uint32_t)(q * 16) * B_STRIDE + (uint32_t)kk * 32);
                    bf[2*q][0] = r4[0]; bf[2*q][1] = r4[2];
                    bf[2*q+1][0] = r4[1]; bf[2*q+1][1] = r4[3];
                }
#pragma unroll
                for (int f = 0; f < 8; f++) mma16(acc[f], a, bf[f]);
            }
            __syncthreads();
            if (gidx + 3 < 64) issueB(gidx + 3);
        }

        // pass epilogue: e = tanh(acc + bias) * Ws
        int o0 = pass * 64;
#pragma unroll
        for (int f = 0; f < 8; f++) {
            int col = o0 + 8 * f + 2 * tg;
            float2 bav = *(const float2*)&ba[ub + col];
            float2 wsv = *(const float2*)&Ws[ub + col];
            float2 Rv  = *(const float2*)&g_R[ub + col];
            float C0 = bav.x - 1e6f * Rv.x;
            float C1 = bav.y - 1e6f * Rv.y;
            pr0 += tanhc(acc[f][0] + (m0 ? C0 : bav.x)) * wsv.x
                 + tanhc(acc[f][1] + (m0 ? C1 : bav.y)) * wsv.y;
            pr1 += tanhc(acc[f][2] + (m1 ? C0 : bav.x)) * wsv.x
                 + tanhc(acc[f][3] + (m1 ? C1 : bav.y)) * wsv.y;
        }
    }

    pr0 += __shfl_xor_sync(0xffffffffu, pr0, 1);
    pr0 += __shfl_xor_sync(0xffffffffu, pr0, 2);
    pr1 += __shfl_xor_sync(0xffffffffu, pr1, 1);
    pr1 += __shfl_xor_sync(0xffffffffu, pr1, 2);
    float bsu = bs[u];
    if (tg == 0) {
        scores_s[16 * w + g]     = pr0 + bsu;
        scores_s[16 * w + 8 + g] = pr1 + bsu;
    }
    __syncthreads();

    if (w == 0) {
        float m = -1e30f;
        for (int s = l; s < S_; s += 32) m = fmaxf(m, scores_s[s]);
#pragma unroll
        for (int off = 16; off > 0; off >>= 1) m = fmaxf(m, __shfl_xor_sync(0xffffffffu, m, off));
        float sum = 0.0f;
        for (int s = l; s < S_; s += 32) {
            float e = __expf(scores_s[s] - m);
            wts[s] = e;
            sum += e;
        }
#pragma unroll
        for (int off = 16; off > 0; off >>= 1) sum += __shfl_xor_sync(0xffffffffu, sum, off);
        if (l == 0) inv_s = 1.0f / sum;
    }
    __syncthreads();

    const float* rb = reps + (size_t)b * S_ * 512;
    float acc0 = 0.0f, acc1 = 0.0f;
    for (int s = 0; s < S_; s++) {
        float wv = wts[s];
        acc0 += wv * rb[(size_t)s * 512 + tid];
        acc1 += wv * rb[(size_t)s * 512 + 256 + tid];
    }
    float inv = inv_s;
    outp[(size_t)b * 512 + tid]       = acc0 * inv;
    outp[(size_t)b * 512 + 256 + tid] = acc1 * inv;
}

// =====================================================================
extern "C" void kernel_launch(void* const* d_in, const int* in_sizes, int n_in,
                              void* d_out, int out_size) {
    (void)in_sizes; (void)n_in; (void)out_size;
    const float* reps   = (const float*)d_in[0];
    const float* hidden = (const float*)d_in[1];
    const int*   counts = (const int*)  d_in[2];
    const int*   users  = (const int*)  d_in[3];
    const float* Wih    = (const float*)d_in[4];
    const float* Whh    = (const float*)d_in[5];
    const float* bih    = (const float*)d_in[6];
    const float* bhh    = (const float*)d_in[7];
    const float* Wa     = (const float*)d_in[8];
    const float* ba     = (const float*)d_in[9];
    const float* Wsc    = (const float*)d_in[10];
    const float* bsc    = (const float*)d_in[11];
    float* outp = (float*)d_out;

    cudaFuncSetAttribute(gru_kernel, cudaFuncAttributeMaxDynamicSharedMemorySize, 2 * GSTG);
    cudaFuncSetAttribute(attn_kernel, cudaFuncAttributeMaxDynamicSharedMemorySize, ATTN_SM);

    prep_x<<<12800, 1024>>>((const float4*)reps);
    prep_h<<<128, 1024>>>((const float4*)hidden);
    prep_w<<<1536, 1024>>>(Whh, Wih);
    prep_wa<<<64000, 256>>>(Wa);
    gru_kernel<<<128, 256, 2 * GSTG>>>(hidden, bhh, bih);
    attn_kernel<<<B_, 256, ATTN_SM>>>(reps, counts, users, ba, Wsc, bsc, outp);
}

// round 8
// speedup vs baseline: 1.3709x; 1.0580x over previous
#include <cuda_runtime.h>
#include <cuda_bf16.h>
#include <cstdint>
#include <cstddef>

#define B_   1024
#define S_   100
#define H_   512
#define NU   1000
#define GRU_CTAS  256
#define PREP_CTAS 744

// ---------------- scratch (static device memory; no allocations) ----------------
__device__ float         g_out[(size_t)B_ * S_ * H_];     // fp32 outputs (own-row recurrence)
__device__ __nv_bfloat16 g_obf[(size_t)B_ * S_ * H_];     // bf16 outputs (cross-CTA A source + attn)
__device__ __nv_bfloat16 g_h0[B_ * H_];                   // initial h bf16
__device__ float         g_xp[(size_t)B_ * S_ * 1536];    // x-projection, per col-tile groups of 96
__device__ __nv_bfloat16 g_wabf[(size_t)NU * H_ * H_];    // Wa bf16
__device__ float         g_R[NU * H_];                    // fp32 Wa row sums
__device__ unsigned char g_wblob[16 * 2 * 4 * 24576];     // GRU W tiles bf16
__device__ unsigned g_gbarc[16];
__device__ unsigned g_gbarg[16];

// ---------------- helpers ----------------
__device__ __forceinline__ void cpa16(uint32_t s, const void* g) {
    asm volatile("cp.async.cg.shared.global [%0], [%1], 16;\n" :: "r"(s), "l"(g));
}
__device__ __forceinline__ void cp_commit() { asm volatile("cp.async.commit_group;\n"); }
template<int N> __device__ __forceinline__ void cp_wait() {
    asm volatile("cp.async.wait_group %0;\n" :: "n"(N));
}
__device__ __forceinline__ float sigf(float x)  { return 1.0f / (1.0f + __expf(-x)); }
__device__ __forceinline__ float tanhc(float x) { return 1.0f - 2.0f / (__expf(2.0f * x) + 1.0f); }

__device__ __forceinline__ void mma16(float c[4], const uint32_t a[4], const uint32_t b[2]) {
    asm volatile(
        "mma.sync.aligned.m16n8k16.row.col.f32.bf16.bf16.f32 "
        "{%0,%1,%2,%3}, {%4,%5,%6,%7}, {%8,%9}, {%0,%1,%2,%3};\n"
        : "+f"(c[0]), "+f"(c[1]), "+f"(c[2]), "+f"(c[3])
        : "r"(a[0]), "r"(a[1]), "r"(a[2]), "r"(a[3]), "r"(b[0]), "r"(b[1]));
}
__device__ __forceinline__ void ldsm4(uint32_t r[4], uint32_t addr) {
    asm volatile("ldmatrix.sync.aligned.m8n8.x4.shared.b16 {%0,%1,%2,%3}, [%4];"
        : "=r"(r[0]), "=r"(r[1]), "=r"(r[2]), "=r"(r[3]) : "r"(addr));
}
__device__ __forceinline__ uint32_t pack_bf(float x, float y) {
    __nv_bfloat162 p = __floats2bfloat162_rn(x, y);
    return *(uint32_t*)&p;
}

// =====================================================================
// Prep kernels
// =====================================================================
__global__ void prep_h0(const float4* __restrict__ Hd) {
    int i = blockIdx.x * 1024 + threadIdx.x;
    if (i < B_ * H_ / 4) {
        float4 v = Hd[i];
        *(uint2*)&g_h0[i * 4] = make_uint2(pack_bf(v.x, v.y), pack_bf(v.z, v.w));
    }
}
// W blobs: [ct 16][phase 2][chunk 4] of 96 rows x 128 k bf16 (row-major 256B rows)
__global__ void prep_w(const float* __restrict__ Whh, const float* __restrict__ Wih) {
    size_t idx = (size_t)blockIdx.x * 1024 + threadIdx.x;
    if (idx >= (size_t)16 * 2 * 4 * 96 * 128) return;
    int k  = (int)(idx & 127);
    size_t i2 = idx >> 7;
    int r = (int)(i2 % 96); size_t i3 = i2 / 96;
    int c = (int)(i3 & 3);
    size_t i4 = i3 >> 2;
    int p  = (int)(i4 & 1);
    int ct = (int)(i4 >> 1);
    const float* W = p ? Wih : Whh;
    int grow = (r >> 5) * 512 + ct * 32 + (r & 31);
    float v = W[(size_t)grow * 512 + c * 128 + k];
    size_t blob = ((size_t)(ct * 2 + p) * 4 + c) * 24576;
    *(__nv_bfloat16*)(g_wblob + blob + (size_t)r * 256 + k * 2) = __float2bfloat16(v);
}

// =====================================================================
// xproj: g_xp[(m*16+ct)*96 + col] = x[m,:] @ Wih_tile(ct)[col,:]^T  (fp32 out)
// m = b*S+t (102400 rows). Tile 64 rows x 96 cols, K=512 (4 chunks of 128).
// 128 threads, 2 CTAs/SM. A read fp32->bf16 inline (reg prefetch), B cp.async.
// =====================================================================
#define XSTG 43520     // stage bytes: A 64x272 + B 96x272

__global__ void __launch_bounds__(128, 2)
xproj_kernel(const float* __restrict__ reps) {
    extern __shared__ unsigned char dsm[];
    const uint32_t smb = (uint32_t)__cvta_generic_to_shared(dsm);

    const int m0 = blockIdx.x * 64;
    const int ct = blockIdx.y;
    const int tid = threadIdx.x;
    const int l   = tid & 31;
    const int w   = tid >> 5;                 // 4 warps, strip rows 16w..16w+15
    const int g   = l >> 2;
    const int tg  = l & 3;
    const uint32_t loff = (uint32_t)((((l >> 3) & 1) * 8 + (l & 7)) * 272 + (l >> 4) * 16);

    // A slots: 2048 float4 per chunk / 128 thr = 16
    int arow[16], ac4[16];
#pragma unroll
    for (int i = 0; i < 16; i++) {
        int u = tid + i * 128;
        arow[i] = u >> 5; ac4[i] = (u & 31) * 4;
    }
    // B slots: 1536 units / 128 thr = 12
    const unsigned char* blobs = g_wblob + ((size_t)(ct * 2 + 1) * 4) * 24576;  // phase 1 (Wih)
    uint32_t bdst[12], bsrc[12];
#pragma unroll
    for (int i = 0; i < 12; i++) {
        int u = tid + i * 128;
        bdst[i] = (uint32_t)(17408 + (u >> 4) * 272 + (u & 15) * 16);
        bsrc[i] = (uint32_t)u * 16;
    }

    auto issueB = [&](int c) {
        uint32_t base = smb + (uint32_t)(c & 1) * XSTG;
        const unsigned char* blob = blobs + (size_t)c * 24576;
#pragma unroll
        for (int i = 0; i < 12; i++) cpa16(base + bdst[i], blob + bsrc[i]);
        cp_commit();
    };
    float4 ra[16];
    auto ldgA = [&](int c) {
#pragma unroll
        for (int i = 0; i < 16; i++)
            ra[i] = *(const float4*)&reps[(size_t)(m0 + arow[i]) * 512 + c * 128 + ac4[i]];
    };
    auto stsA = [&](int c) {
        unsigned char* dst = dsm + (size_t)(c & 1) * XSTG;
#pragma unroll
        for (int i = 0; i < 16; i++) {
            float4 v = ra[i];
            *(uint2*)(dst + arow[i] * 272 + ac4[i] * 2) =
                make_uint2(pack_bf(v.x, v.y), pack_bf(v.z, v.w));
        }
    };

    float acc[12][4];
#pragma unroll
    for (int i = 0; i < 12; i++)
#pragma unroll
        for (int j = 0; j < 4; j++) acc[i][j] = 0.0f;

    ldgA(0);
    issueB(0); issueB(1);
    for (int c = 0; c < 4; c++) {
        stsA(c);
        if (c < 3) ldgA(c + 1);
        if (c < 3) cp_wait<1>(); else cp_wait<0>();
        __syncthreads();
        uint32_t Ab = smb + (uint32_t)(c & 1) * XSTG + (uint32_t)(w * 16) * 272 + loff;
        uint32_t Bb = smb + (uint32_t)(c & 1) * XSTG + 17408 + loff;
#pragma unroll
        for (int kk = 0; kk < 8; kk++) {
            uint32_t kb = (uint32_t)kk * 32;
            uint32_t a[4]; ldsm4(a, Ab + kb);
#pragma unroll
            for (int q = 0; q < 6; q++) {
                uint32_t r4[4]; ldsm4(r4, Bb + (uint32_t)(q * 16) * 272 + kb);
                uint32_t b0[2] = { r4[0], r4[2] }, b1[2] = { r4[1], r4[3] };
                mma16(acc[2 * q], a, b0);
                mma16(acc[2 * q + 1], a, b1);
            }
        }
        __syncthreads();
        if (c < 2) issueB(c + 2);
    }

    // write fp32 results
#pragma unroll
    for (int f = 0; f < 12; f++) {
        int col = 8 * f + 2 * tg;
        size_t m = (size_t)(m0 + 16 * w + g);
        *(float2*)&g_xp[(m * 16 + ct) * 96 + col] = make_float2(acc[f][0], acc[f][1]);
        *(float2*)&g_xp[((m + 8) * 16 + ct) * 96 + col] = make_float2(acc[f][2], acc[f][3]);
    }
}

// =====================================================================
// Persistent GRU (serial K=512 h-GEMM only) + fused Wa-prep CTAs.
// GRU: 256 CTAs = 16 batch-groups(64 rows) x 16 col-tiles(32 hcols = 96 gate rows).
// 128 threads, 2 CTAs/SM GUARANTEED (smem 112640, regs<=256). 16 barrier groups.
// xp tile (64x96 fp32) cp.async-prefetched per step. In-register gate epilogue.
// prep CTAs (bid>=256): Wa fp32 -> bf16 + row sums.
// =====================================================================
#define GSTG   43520
#define XPOFF  87040   // xp region byte offset (64 x 100 fp32)

__global__ void __launch_bounds__(128, 2)
gru_kernel(const float* __restrict__ hidden,
           const float* __restrict__ bhh,
           const float* __restrict__ bih,
           const float* __restrict__ Wa) {
    const int cta = blockIdx.x;
    const int tid = threadIdx.x;

    if (cta >= GRU_CTAS) {
        // ---------- fused Wa prep ----------
        int wp = tid >> 5, lane = tid & 31;
        for (int gw = (cta - GRU_CTAS) * 4 + wp; gw < NU * 512; gw += PREP_CTAS * 4) {
            const float* src = Wa + (size_t)gw * 512;
            __nv_bfloat16* dst = g_wabf + (size_t)gw * 512;
            float s = 0.0f;
#pragma unroll
            for (int i = 0; i < 4; i++) {
                float4 v = *(const float4*)&src[(lane + i * 32) * 4];
                s += v.x + v.y + v.z + v.w;
                *(uint2*)&dst[(lane + i * 32) * 4] =
                    make_uint2(pack_bf(v.x, v.y), pack_bf(v.z, v.w));
            }
#pragma unroll
            for (int off = 16; off > 0; off >>= 1) s += __shfl_xor_sync(0xffffffffu, s, off);
            if (lane == 0) g_R[gw] = s;
        }
        return;
    }

    // ---------- GRU ----------
    extern __shared__ unsigned char dsm[];
    const uint32_t smb = (uint32_t)__cvta_generic_to_shared(dsm);
    __shared__ float sb[128];
    float* xp = (float*)(dsm + XPOFF);

    const int bg   = cta >> 4;
    const int ct   = cta & 15;
    const int b0   = bg * 64;
    const int col0 = ct * 32;
    const int l    = tid & 31;
    const int w    = tid >> 5;
    const int g    = l >> 2;
    const int tg   = l & 3;
    const uint32_t loff = (uint32_t)((((l >> 3) & 1) * 8 + (l & 7)) * 272 + (l >> 4) * 16);

    // loader slots
    int arow[8], aku[8];
#pragma unroll
    for (int i = 0; i < 8; i++) {
        int u = tid + i * 128;
        arow[i] = u >> 4; aku[i] = u & 15;
    }
    uint32_t bdst[12], bsrc[12];
#pragma unroll
    for (int i = 0; i < 12; i++) {
        int u = tid + i * 128;
        bdst[i] = (uint32_t)(17408 + (u >> 4) * 272 + (u & 15) * 16);
        bsrc[i] = (uint32_t)u * 16;
    }
    int xr_[12], xc_[12];
#pragma unroll
    for (int i = 0; i < 12; i++) {
        int u = tid + i * 128;              // 1536 units (64 rows x 24)
        xr_[i] = u / 24; xc_[i] = u % 24;
    }
    const unsigned char* blobs = g_wblob + ((size_t)(ct * 2 + 0) * 4) * 24576;  // phase 0 (Whh)

    if (tid < 32) {
        int jc = col0 + tid;
        sb[tid]      = bih[jc] + bhh[jc];
        sb[32 + tid] = bih[512 + jc] + bhh[512 + jc];
        sb[64 + tid] = bhh[1024 + jc];
        sb[96 + tid] = bih[1024 + jc];
    }
    __syncthreads();

    unsigned gen = *((volatile unsigned*)&g_gbarg[bg]);

    for (int t = 0; t < S_; t++) {
        // xp prefetch (group 0)
#pragma unroll
        for (int i = 0; i < 12; i++) {
            size_t m = (size_t)(b0 + xr_[i]) * S_ + t;
            cpa16(smb + XPOFF + (uint32_t)(xr_[i] * 400 + xc_[i] * 16),
                  g_xp + (m * 16 + ct) * 96 + xc_[i] * 4);
        }
        cp_commit();

        auto issue = [&](int c) {
            uint32_t base = smb + (uint32_t)(c & 1) * GSTG;
            if (t == 0) {
#pragma unroll
                for (int i = 0; i < 8; i++)
                    cpa16(base + (uint32_t)(arow[i] * 272 + aku[i] * 16),
                          g_h0 + (size_t)(b0 + arow[i]) * 512 + c * 128 + aku[i] * 8);
            } else {
#pragma unroll
                for (int i = 0; i < 8; i++)
                    cpa16(base + (uint32_t)(arow[i] * 272 + aku[i] * 16),
                          g_obf + ((size_t)(b0 + arow[i]) * S_ + (t - 1)) * 512 + c * 128 + aku[i] * 8);
            }
            const unsigned char* blob = blobs + (size_t)c * 24576;
#pragma unroll
            for (int i = 0; i < 12; i++) cpa16(base + bdst[i], blob + bsrc[i]);
            cp_commit();
        };

        float acc[12][4];
#pragma unroll
        for (int i = 0; i < 12; i++)
#pragma unroll
            for (int j = 0; j < 4; j++) acc[i][j] = 0.0f;

        issue(0); issue(1);
        for (int c = 0; c < 4; c++) {
            if (c < 3) cp_wait<1>(); else cp_wait<0>();
            __syncthreads();
            uint32_t Ab = smb + (uint32_t)(c & 1) * GSTG + (uint32_t)(w * 16) * 272 + loff;
            uint32_t Bb = smb + (uint32_t)(c & 1) * GSTG + 17408 + loff;
#pragma unroll
            for (int kk = 0; kk < 8; kk++) {
                uint32_t kb = (uint32_t)kk * 32;
                uint32_t a[4]; ldsm4(a, Ab + kb);
#pragma unroll
                for (int q = 0; q < 6; q++) {
                    uint32_t r4[4]; ldsm4(r4, Bb + (uint32_t)(q * 16) * 272 + kb);
                    uint32_t b0f[2] = { r4[0], r4[2] }, b1f[2] = { r4[1], r4[3] };
                    mma16(acc[2 * q], a, b0f);
                    mma16(acc[2 * q + 1], a, b1f);
                }
            }
            __syncthreads();
            if (c < 2) issue(c + 2);
        }

        // ---- in-register gates (frags: 0-3 r, 4-7 z, 8-11 nh; x-part from xp smem) ----
#pragma unroll
        for (int half = 0; half < 2; half++) {
            int lrow = 16 * w + g + half * 8;
            int rr = b0 + lrow;
            const float* hp = (t == 0)
                ? hidden + (size_t)rr * 512 + col0
                : g_out + ((size_t)rr * S_ + (t - 1)) * 512 + col0;
            float* op = g_out + ((size_t)rr * S_ + t) * 512 + col0;
            __nv_bfloat16* ob = g_obf + ((size_t)rr * S_ + t) * 512 + col0;
            const float* xrow = xp + lrow * 100;
#pragma unroll
            for (int q = 0; q < 4; q++) {
                int j = 8 * q + 2 * tg;
                float2 hv  = *(const float2*)(hp + j);
                float2 xr2 = *(const float2*)(xrow + j);
                float2 xz2 = *(const float2*)(xrow + 32 + j);
                float2 xn2 = *(const float2*)(xrow + 64 + j);
                float r0 = sigf(xr2.x + acc[q][2*half + 0] + sb[j]);
                float r1 = sigf(xr2.y + acc[q][2*half + 1] + sb[j + 1]);
                float z0 = sigf(xz2.x + acc[4 + q][2*half + 0] + sb[32 + j]);
                float z1 = sigf(xz2.y + acc[4 + q][2*half + 1] + sb[32 + j + 1]);
                float n0 = tanhc((xn2.x + sb[96 + j])     + r0 * (acc[8 + q][2*half + 0] + sb[64 + j]));
                float n1 = tanhc((xn2.y + sb[96 + j + 1]) + r1 * (acc[8 + q][2*half + 1] + sb[64 + j + 1]));
                float o0 = (1.0f - z0) * n0 + z0 * hv.x;
                float o1 = (1.0f - z1) * n1 + z1 * hv.y;
                *(float2*)(op + j) = make_float2(o0, o1);
                *(uint32_t*)(ob + j) = pack_bf(o0, o1);
            }
        }

        // ---- group barrier (16 CTAs of this batch group) ----
        if (t < S_ - 1) {
            __syncthreads();
            if (tid == 0) {
                unsigned target = gen + 1;
                __threadfence();
                if (atomicAdd(&g_gbarc[bg], 1u) == 15u) {
                    g_gbarc[bg] = 0;
                    __threadfence();
                    atomicExch(&g_gbarg[bg], target);
                } else {
                    while (*((volatile unsigned*)&g_gbarg[bg]) != target) __nanosleep(32);
                    __threadfence();
                }
                gen = target;
            }
            __syncthreads();
        }
    }
}

// =====================================================================
// Attention: A = g_obf (bf16) direct, masked rows fixed up in smem.
// Wa bf16 streamed 4-deep. 8 o-passes of 64 cols.
// =====================================================================
#define A_STRIDE 1040
#define B_STRIDE 144
#define B_STG    9216
#define ATTN_SM  (133120 + 4 * B_STG)

__global__ void __launch_bounds__(256)
attn_kernel(const float* __restrict__ reps,
            const int*   __restrict__ counts,
            const int*   __restrict__ users,
            const float* __restrict__ ba,
            const float* __restrict__ Ws,
            const float* __restrict__ bs,
            float*       __restrict__ outp) {
    extern __shared__ unsigned char dsm[];
    const uint32_t smb = (uint32_t)__cvta_generic_to_shared(dsm);
    __shared__ float scores_s[128];
    __shared__ float wts[S_];
    __shared__ float inv_s;

    const int b   = blockIdx.x;
    const int u   = users[b];
    const int cnt = counts[b];
    const size_t ub = (size_t)u * 512;
    const __nv_bfloat16* wab = g_wabf + (size_t)u * 512 * 512;

    const int tid = threadIdx.x;
    const int l   = tid & 31;
    const int w   = tid >> 5;
    const int g   = l >> 2;
    const int tg  = l & 3;
    const uint32_t loffA = (uint32_t)((((l >> 3) & 1) * 8 + (l & 7)) * A_STRIDE + (l >> 4) * 16);
    const uint32_t loffB = (uint32_t)((((l >> 3) & 1) * 8 + (l & 7)) * B_STRIDE + (l >> 4) * 16);

    int rB[2], kuB[2];
#pragma unroll
    for (int i = 0; i < 2; i++) {
        int uu = tid + i * 256;
        rB[i] = uu >> 3; kuB[i] = uu & 7;
    }
    auto issueB = [&](int gidx) {
        int pass = gidx >> 3, c = gidx & 7;
        uint32_t base = smb + 133120 + (uint32_t)(gidx & 3) * B_STG;
#pragma unroll
        for (int i = 0; i < 2; i++)
            cpa16(base + (uint32_t)(rB[i] * B_STRIDE + kuB[i] * 16),
                  wab + (size_t)(pass * 64 + rB[i]) * 512 + c * 64 + kuB[i] * 8);
        cp_commit();
    };

    issueB(0); issueB(1); issueB(2);

    // ---- load A (bf16) rows 0..99 directly; 25 16B units/thread ----
#pragma unroll
    for (int i = 0; i < 25; i++) {
        int uu = tid + i * 256;
        int row = uu >> 6, cu = uu & 63;
        uint4 v = *(const uint4*)&g_obf[((size_t)b * S_ + row) * 512 + cu * 8];
        *(uint4*)(dsm + row * A_STRIDE + cu * 16) = v;
    }
    __syncthreads();
    // ---- masked-row fixup: rows cnt..99 get (v - 1e6) + 1e6 quantization ----
    {
        int nwords = (S_ - cnt) * 256;
        for (int widx = tid; widx < nwords; widx += 256) {
            int row = cnt + (widx >> 8), cw = widx & 255;
            uint32_t* p = (uint32_t*)(dsm + row * A_STRIDE + cw * 4);
            uint32_t pv = *p;
            __nv_bfloat162 bv = *(__nv_bfloat162*)&pv;
            float vx = (__bfloat162float(bv.x) - 1e6f) + 1e6f;
            float vy = (__bfloat162float(bv.y) - 1e6f) + 1e6f;
            *p = pack_bf(vx, vy);
        }
    }
    __syncthreads();

    const bool m0 = (16 * w + g >= cnt);
    const bool m1 = (16 * w + 8 + g >= cnt);
    float pr0 = 0.0f, pr1 = 0.0f;

    for (int pass = 0; pass < 8; pass++) {
        float acc[8][4];
#pragma unroll
        for (int i = 0; i < 8; i++)
#pragma unroll
            for (int j = 0; j < 4; j++) acc[i][j] = 0.0f;

        for (int c = 0; c < 8; c++) {
            int gidx = pass * 8 + c;
            if (gidx < 62) cp_wait<2>();
            else if (gidx == 62) cp_wait<1>();
            else cp_wait<0>();
            __syncthreads();
            uint32_t Ab = smb + (uint32_t)(w * 16) * A_STRIDE + loffA + (uint32_t)(c * 64) * 2;
            uint32_t Bb = smb + 133120 + (uint32_t)(gidx & 3) * B_STG + loffB;
#pragma unroll
            for (int kk = 0; kk < 4; kk++) {
                uint32_t a[4]; ldsm4(a, Ab + (uint32_t)kk * 32);
#pragma unroll
                for (int q = 0; q < 4; q++) {
                    uint32_t r4[4];
                    ldsm4(r4, Bb + (uint32_t)(q * 16) * B_STRIDE + (uint32_t)kk * 32);
                    uint32_t b0f[2] = { r4[0], r4[2] }, b1f[2] = { r4[1], r4[3] };
                    mma16(acc[2 * q], a, b0f);
                    mma16(acc[2 * q + 1], a, b1f);
                }
            }
            __syncthreads();
            if (gidx + 3 < 64) issueB(gidx + 3);
        }

        int o0 = pass * 64;
#pragma unroll
        for (int f = 0; f < 8; f++) {
            int col = o0 + 8 * f + 2 * tg;
            float2 bav = *(const float2*)&ba[ub + col];
            float2 wsv = *(const float2*)&Ws[ub + col];
            float2 Rv  = *(const float2*)&g_R[ub + col];
            float C0 = bav.x - 1e6f * Rv.x;
            float C1 = bav.y - 1e6f * Rv.y;
            pr0 += tanhc(acc[f][0] + (m0 ? C0 : bav.x)) * wsv.x
                 + tanhc(acc[f][1] + (m0 ? C1 : bav.y)) * wsv.y;
            pr1 += tanhc(acc[f][2] + (m1 ? C0 : bav.x)) * wsv.x
                 + tanhc(acc[f][3] + (m1 ? C1 : bav.y)) * wsv.y;
        }
    }

    pr0 += __shfl_xor_sync(0xffffffffu, pr0, 1);
    pr0 += __shfl_xor_sync(0xffffffffu, pr0, 2);
    pr1 += __shfl_xor_sync(0xffffffffu, pr1, 1);
    pr1 += __shfl_xor_sync(0xffffffffu, pr1, 2);
    float bsu = bs[u];
    if (tg == 0) {
        scores_s[16 * w + g]     = pr0 + bsu;
        scores_s[16 * w + 8 + g] = pr1 + bsu;
    }
    __syncthreads();

    if (w == 0) {
        float m = -1e30f;
        for (int s = l; s < S_; s += 32) m = fmaxf(m, scores_s[s]);
#pragma unroll
        for (int off = 16; off > 0; off >>= 1) m = fmaxf(m, __shfl_xor_sync(0xffffffffu, m, off));
        float sum = 0.0f;
        for (int s = l; s < S_; s += 32) {
            float e = __expf(scores_s[s] - m);
            wts[s] = e;
            sum += e;
        }
#pragma unroll
        for (int off = 16; off > 0; off >>= 1) sum += __shfl_xor_sync(0xffffffffu, sum, off);
        if (l == 0) inv_s = 1.0f / sum;
    }
    __syncthreads();

    const float* rb = reps + (size_t)b * S_ * 512;
    float acc0 = 0.0f, acc1 = 0.0f;
    for (int s = 0; s < S_; s++) {
        float wv = wts[s];
        acc0 += wv * rb[(size_t)s * 512 + tid];
        acc1 += wv * rb[(size_t)s * 512 + 256 + tid];
    }
    float inv = inv_s;
    outp[(size_t)b * 512 + tid]       = acc0 * inv;
    outp[(size_t)b * 512 + 256 + tid] = acc1 * inv;
}

// =====================================================================
extern "C" void kernel_launch(void* const* d_in, const int* in_sizes, int n_in,
                              void* d_out, int out_size) {
    (void)in_sizes; (void)n_in; (void)out_size;
    const float* reps   = (const float*)d_in[0];
    const float* hidden = (const float*)d_in[1];
    const int*   counts = (const int*)  d_in[2];
    const int*   users  = (const int*)  d_in[3];
    const float* Wih    = (const float*)d_in[4];
    const float* Whh    = (const float*)d_in[5];
    const float* bih    = (const float*)d_in[6];
    const float* bhh    = (const float*)d_in[7];
    const float* Wa     = (const float*)d_in[8];
    const float* ba     = (const float*)d_in[9];
    const float* Wsc    = (const float*)d_in[10];
    const float* bsc    = (const float*)d_in[11];
    float* outp = (float*)d_out;

    cudaFuncSetAttribute(xproj_kernel, cudaFuncAttributeMaxDynamicSharedMemorySize, 2 * XSTG);
    cudaFuncSetAttribute(gru_kernel, cudaFuncAttributeMaxDynamicSharedMemorySize, XPOFF + 25600);
    cudaFuncSetAttribute(attn_kernel, cudaFuncAttributeMaxDynamicSharedMemorySize, ATTN_SM);

    prep_h0<<<128, 1024>>>((const float4*)hidden);
    prep_w<<<1536, 1024>>>(Whh, Wih);
    xproj_kernel<<<dim3(1600, 16), 128, 2 * XSTG>>>(reps);
    gru_kernel<<<GRU_CTAS + PREP_CTAS, 128, XPOFF + 25600>>>(hidden, bhh, bih, Wa);
    attn_kernel<<<B_, 256, ATTN_SM>>>(reps, counts, users, ba, Wsc, bsc, outp);
}